// round 15
// baseline (speedup 1.0000x reference)
#include <cuda_runtime.h>
#include <cuda_bf16.h>
#include <mma.h>
#include <math.h>
#include <stdint.h>

using namespace nvcuda;

#define U_NUM 100000
#define I_NUM 50000
#define N_NUM 150000
#define E_NUM 1200000
#define D 64
#define F_DIM 384
#define EPS 1e-8f
#define ELL_W 64

// Scratch (allocation-free rule: __device__ globals; zero-initialized at load)
// cnt invariant: zero at entry to every kernel_launch call (zero-init at load;
// final layer re-zeroes after its read on every call).
__device__ float g_ego[(size_t)N_NUM * D];
__device__ float g_buf0[(size_t)N_NUM * D];
__device__ float g_buf1[(size_t)N_NUM * D];
__device__ float g_buf2[(size_t)N_NUM * D];
__device__ int   g_cnt[N_NUM];
__device__ int2  g_elle[(size_t)N_NUM * ELL_W];   // packed (col, val-bits); tail slots stay 0
__device__ int            g_bar_cnt;              // grid barrier arrivals
__device__ volatile unsigned g_bar_gen;           // grid barrier generation

__device__ __forceinline__ float tanh_fast(float x) {
    float r;
    asm("tanh.approx.f32 %0, %1;" : "=f"(r) : "f"(x));
    return r;
}

// ---- L2 cache-hint policies (createpolicy + cache_hint form)
__device__ __forceinline__ uint64_t mk_policy_last() {
    uint64_t p;
    asm("createpolicy.fractional.L2::evict_last.b64 %0, 1.0;" : "=l"(p));
    return p;
}
__device__ __forceinline__ uint64_t mk_policy_first() {
    uint64_t p;
    asm("createpolicy.fractional.L2::evict_first.b64 %0, 1.0;" : "=l"(p));
    return p;
}
__device__ __forceinline__ float4 ldg_f4_pol(const float4* p, uint64_t pol) {
    float4 v;
    asm("ld.global.nc.L2::cache_hint.v4.f32 {%0,%1,%2,%3}, [%4], %5;"
        : "=f"(v.x), "=f"(v.y), "=f"(v.z), "=f"(v.w) : "l"(p), "l"(pol));
    return v;
}
__device__ __forceinline__ int4 ldg_i4_pol(const int4* p, uint64_t pol) {
    int4 v;
    asm("ld.global.nc.L2::cache_hint.v4.b32 {%0,%1,%2,%3}, [%4], %5;"
        : "=r"(v.x), "=r"(v.y), "=r"(v.z), "=r"(v.w) : "l"(p), "l"(pol));
    return v;
}
__device__ __forceinline__ void stg_f4_pol(float4* p, float4 v, uint64_t pol) {
    asm volatile("st.global.L2::cache_hint.v4.f32 [%0], {%1,%2,%3,%4}, %5;"
                 :: "l"(p), "f"(v.x), "f"(v.y), "f"(v.z), "f"(v.w), "l"(pol) : "memory");
}

// ---- grid-wide barrier (all blocks resident by construction: grid sized via
// occupancy API). Generation-counter protocol; last arrival releases.
__device__ __forceinline__ void grid_barrier(int nblocks) {
    __syncthreads();
    if (threadIdx.x == 0) {
        __threadfence();
        unsigned gen = g_bar_gen;
        if (atomicAdd(&g_bar_cnt, 1) == nblocks - 1) {
            g_bar_cnt = 0;
            __threadfence();
            g_bar_gen = gen + 1;
        } else {
            while (g_bar_gen == gen) { }
        }
        __threadfence();
    }
    __syncthreads();
}

// ---------------- fused preamble: [gemm tiles | ELL build | user init], one kernel
#define BM 128
#define GK 32
#define LDA 40
#define LDW 40

#define GEMM_BLOCKS ((I_NUM + BM - 1) / BM)   // 391
#define BUILD_BLOCKS 320
#define USER_BLOCKS  320
#define PRE_BLOCKS (GEMM_BLOCKS + BUILD_BLOCKS + USER_BLOCKS)

#define SM_AS_HI 0
#define SM_AS_LO (SM_AS_HI + BM * LDA * 2)            // 10240
#define SM_WS_HI (SM_AS_LO + BM * LDA * 2)            // 20480
#define SM_WS_LO (SM_WS_HI + D * LDW * 2)             // 25600
#define SM_MAIN  (SM_WS_LO + D * LDW * 2)             // 30720
#define SM_TOTAL SM_MAIN                               // epilogue tile (8KB) overlaps staging

__device__ __forceinline__ void split_store(__nv_bfloat16* hi, __nv_bfloat16* lo, float v) {
    __nv_bfloat16 h = __float2bfloat16(v);
    *hi = h;
    *lo = __float2bfloat16(v - __bfloat162float(h));
}

__global__ __launch_bounds__(256) void k_preamble(
    const float* __restrict__ A,
    const float* __restrict__ W,
    const float* __restrict__ bias,
    const float* __restrict__ gi,
    const int* __restrict__ rows, const int* __restrict__ cols,
    const float* __restrict__ vals,
    const float* __restrict__ user_fea,
    const float* __restrict__ gu,
    int* __restrict__ cnt, int2* __restrict__ elle,
    float* __restrict__ ego) {
    __shared__ __align__(16) char smem[SM_TOTAL];
    int blk = blockIdx.x;
    int t = threadIdx.x;

    if (blk < GEMM_BLOCKS) {
        __nv_bfloat16 (*AsH)[LDA] = (__nv_bfloat16(*)[LDA])(smem + SM_AS_HI);
        __nv_bfloat16 (*AsL)[LDA] = (__nv_bfloat16(*)[LDA])(smem + SM_AS_LO);
        __nv_bfloat16 (*WsH)[LDW] = (__nv_bfloat16(*)[LDW])(smem + SM_WS_HI);
        __nv_bfloat16 (*WsL)[LDW] = (__nv_bfloat16(*)[LDW])(smem + SM_WS_LO);

        int w = t >> 5;
        int lane = t & 31;
        int r0 = blk * BM;

        wmma::fragment<wmma::accumulator, 16, 16, 16, float> cfrag[4];
        #pragma unroll
        for (int nf = 0; nf < 4; nf++) wmma::fill_fragment(cfrag[nf], 0.0f);

        int ar = t >> 1,  ac = (t & 1) * 16;
        int wr = t >> 2,  wc = (t & 3) * 8;

        for (int k0 = 0; k0 < F_DIM; k0 += GK) {
            {
                int gr = r0 + ar;
                if (gr < I_NUM) {
                    const float4* src = (const float4*)(A + (size_t)gr * F_DIM + k0 + ac);
                    #pragma unroll
                    for (int s = 0; s < 4; s++) {
                        float4 v = __ldg(src + s);
                        split_store(&AsH[ar][ac + s * 4],     &AsL[ar][ac + s * 4],     v.x);
                        split_store(&AsH[ar][ac + s * 4 + 1], &AsL[ar][ac + s * 4 + 1], v.y);
                        split_store(&AsH[ar][ac + s * 4 + 2], &AsL[ar][ac + s * 4 + 2], v.z);
                        split_store(&AsH[ar][ac + s * 4 + 3], &AsL[ar][ac + s * 4 + 3], v.w);
                    }
                } else {
                    #pragma unroll
                    for (int s = 0; s < 16; s++) {
                        AsH[ar][ac + s] = __float2bfloat16(0.f);
                        AsL[ar][ac + s] = __float2bfloat16(0.f);
                    }
                }
            }
            {
                const float4* src = (const float4*)(W + (size_t)wr * F_DIM + k0 + wc);
                #pragma unroll
                for (int s = 0; s < 2; s++) {
                    float4 v = __ldg(src + s);
                    split_store(&WsH[wr][wc + s * 4],     &WsL[wr][wc + s * 4],     v.x);
                    split_store(&WsH[wr][wc + s * 4 + 1], &WsL[wr][wc + s * 4 + 1], v.y);
                    split_store(&WsH[wr][wc + s * 4 + 2], &WsL[wr][wc + s * 4 + 2], v.z);
                    split_store(&WsH[wr][wc + s * 4 + 3], &WsL[wr][wc + s * 4 + 3], v.w);
                }
            }
            __syncthreads();

            #pragma unroll
            for (int kk = 0; kk < GK; kk += 16) {
                wmma::fragment<wmma::matrix_a, 16, 16, 16, __nv_bfloat16, wmma::row_major> aH, aL;
                wmma::load_matrix_sync(aH, &AsH[w * 16][kk], LDA);
                wmma::load_matrix_sync(aL, &AsL[w * 16][kk], LDA);
                #pragma unroll
                for (int nf = 0; nf < 4; nf++) {
                    wmma::fragment<wmma::matrix_b, 16, 16, 16, __nv_bfloat16, wmma::col_major> bH, bL;
                    wmma::load_matrix_sync(bH, &WsH[nf * 16][kk], LDW);
                    wmma::load_matrix_sync(bL, &WsL[nf * 16][kk], LDW);
                    wmma::mma_sync(cfrag[nf], aH, bH, cfrag[nf]);
                    wmma::mma_sync(cfrag[nf], aH, bL, cfrag[nf]);
                    wmma::mma_sync(cfrag[nf], aL, bH, cfrag[nf]);
                }
            }
            __syncthreads();
        }

        // epilogue: per-warp 16x16 tile stash, sequential over nf (8KB total, in smem)
        float (*OsW)[16][16] = (float(*)[16][16])smem;   // [warp][i][j]
        __syncthreads();  // staging no longer needed; reuse smem
        #pragma unroll
        for (int nf = 0; nf < 4; nf++) {
            wmma::store_matrix_sync(&OsW[w][0][0], cfrag[nf], 16, wmma::mem_row_major);
            __syncwarp();
            for (int idx = lane; idx < 16 * 16; idx += 32) {
                int i = idx >> 4;
                int n = nf * 16 + (idx & 15);
                int r = r0 + w * 16 + i;
                if (r < I_NUM) {
                    float c = OsW[w][i][idx & 15];
                    float sn = gi[n] + gi[D + n] + gi[2 * D + n];
                    ego[(size_t)(U_NUM + r) * D + n] = tanh_fast(c + bias[n]) + sn;
                }
            }
            __syncwarp();
        }
    } else if (blk < GEMM_BLOCKS + BUILD_BLOCKS) {
        int base = (blk - GEMM_BLOCKS) * 256 + t;
        for (int e = base; e < E_NUM; e += BUILD_BLOCKS * 256) {
            int r = __ldg(rows + e);
            int slot = atomicAdd(cnt + r, 1);
            if (slot < ELL_W) {
                int2 p;
                p.x = __ldg(cols + e);
                p.y = __float_as_int(__ldg(vals + e));
                elle[(size_t)r * ELL_W + slot] = p;
            }
        }
    } else {
        int wbase = (blk - GEMM_BLOCKS - BUILD_BLOCKS) * 8 + (t >> 5);
        int lane = t & 31;
        int d0 = lane * 2;
        float s0 = gu[d0]     + gu[D + d0]     + gu[2 * D + d0];
        float s1 = gu[d0 + 1] + gu[D + d0 + 1] + gu[2 * D + d0 + 1];
        for (int u = wbase; u < U_NUM; u += USER_BLOCKS * 8) {
            float2 v = ((const float2*)(user_fea + (size_t)u * D))[lane];
            v.x += s0; v.y += s1;
            ((float2*)(ego + (size_t)u * D))[lane] = v;
        }
    }
}

// ---------------- persistent 4-layer kernel: half-warp per row, grid barrier
// between layers. R14 body. Final layer fuses acc combine + cnt re-zero.
__global__ __launch_bounds__(256) void k_layers(
    const float* __restrict__ ego,
    float* __restrict__ b0, float* __restrict__ b1, float* __restrict__ b2,
    float* __restrict__ accout,
    int* __restrict__ cnt, const int2* __restrict__ elle, int nblocks) {

    uint64_t pL = mk_policy_last();
    uint64_t pF = mk_policy_first();
    int hl = threadIdx.x & 15;
    int slot0 = (blockIdx.x * blockDim.x + threadIdx.x) >> 4;  // global half-warp id
    int nslots = (nblocks * 256) >> 4;

    #pragma unroll
    for (int l = 0; l < 4; l++) {
        const float* x = (l == 0) ? ego : (l == 1) ? b0 : (l == 2) ? b1 : b2;
        float* y = (l == 0) ? b0 : (l == 1) ? b1 : (l == 2) ? b2 : accout;
        const bool FIN = (l == 3);

        for (int row = slot0; row < N_NUM; row += nslots) {
            int c = min(__ldg((const int*)cnt + row), ELL_W);
            const int4* ep4 = (const int4*)(elle + (size_t)row * ELL_W);
            float4 acc = make_float4(0.f, 0.f, 0.f, 0.f);

            int b = 0;
            do {
                int q = b >> 1;
                int4 q0 = ldg_i4_pol(ep4 + q,     pF);
                int4 q1 = ldg_i4_pol(ep4 + q + 1, pF);
                int4 q2 = ldg_i4_pol(ep4 + q + 2, pF);
                int4 q3 = ldg_i4_pol(ep4 + q + 3, pF);
                float4 x0 = ldg_f4_pol((const float4*)(x + (size_t)q0.x * D) + hl, pL);
                float4 x1 = ldg_f4_pol((const float4*)(x + (size_t)q0.z * D) + hl, pL);
                float4 x2 = ldg_f4_pol((const float4*)(x + (size_t)q1.x * D) + hl, pL);
                float4 x3 = ldg_f4_pol((const float4*)(x + (size_t)q1.z * D) + hl, pL);
                float4 x4 = ldg_f4_pol((const float4*)(x + (size_t)q2.x * D) + hl, pL);
                float4 x5 = ldg_f4_pol((const float4*)(x + (size_t)q2.z * D) + hl, pL);
                float4 x6 = ldg_f4_pol((const float4*)(x + (size_t)q3.x * D) + hl, pL);
                float4 x7 = ldg_f4_pol((const float4*)(x + (size_t)q3.z * D) + hl, pL);
                float v0 = __int_as_float(q0.y), v1 = __int_as_float(q0.w);
                float v2 = __int_as_float(q1.y), v3 = __int_as_float(q1.w);
                float v4 = __int_as_float(q2.y), v5 = __int_as_float(q2.w);
                float v6 = __int_as_float(q3.y), v7 = __int_as_float(q3.w);
                acc.x = fmaf(v0, x0.x, acc.x); acc.y = fmaf(v0, x0.y, acc.y);
                acc.z = fmaf(v0, x0.z, acc.z); acc.w = fmaf(v0, x0.w, acc.w);
                acc.x = fmaf(v1, x1.x, acc.x); acc.y = fmaf(v1, x1.y, acc.y);
                acc.z = fmaf(v1, x1.z, acc.z); acc.w = fmaf(v1, x1.w, acc.w);
                acc.x = fmaf(v2, x2.x, acc.x); acc.y = fmaf(v2, x2.y, acc.y);
                acc.z = fmaf(v2, x2.z, acc.z); acc.w = fmaf(v2, x2.w, acc.w);
                acc.x = fmaf(v3, x3.x, acc.x); acc.y = fmaf(v3, x3.y, acc.y);
                acc.z = fmaf(v3, x3.z, acc.z); acc.w = fmaf(v3, x3.w, acc.w);
                acc.x = fmaf(v4, x4.x, acc.x); acc.y = fmaf(v4, x4.y, acc.y);
                acc.z = fmaf(v4, x4.z, acc.z); acc.w = fmaf(v4, x4.w, acc.w);
                acc.x = fmaf(v5, x5.x, acc.x); acc.y = fmaf(v5, x5.y, acc.y);
                acc.z = fmaf(v5, x5.z, acc.z); acc.w = fmaf(v5, x5.w, acc.w);
                acc.x = fmaf(v6, x6.x, acc.x); acc.y = fmaf(v6, x6.y, acc.y);
                acc.z = fmaf(v6, x6.z, acc.z); acc.w = fmaf(v6, x6.w, acc.w);
                acc.x = fmaf(v7, x7.x, acc.x); acc.y = fmaf(v7, x7.y, acc.y);
                acc.z = fmaf(v7, x7.z, acc.z); acc.w = fmaf(v7, x7.w, acc.w);
                b += 8;
            } while (b < c);

            size_t base = (size_t)row * D;
            float4 ev = ldg_f4_pol((const float4*)(ego + base) + hl, pF);
            float dot = acc.x * ev.x + acc.y * ev.y + acc.z * ev.z + acc.w * ev.w;
            float ssy = acc.x * acc.x + acc.y * acc.y + acc.z * acc.z + acc.w * acc.w;
            float sse = ev.x * ev.x + ev.y * ev.y + ev.z * ev.z + ev.w * ev.w;
            #pragma unroll
            for (int o = 8; o; o >>= 1) {
                dot += __shfl_xor_sync(0xffffffffu, dot, o);
                ssy += __shfl_xor_sync(0xffffffffu, ssy, o);
                sse += __shfl_xor_sync(0xffffffffu, sse, o);
            }
            float w = dot / (fmaxf(sqrtf(ssy), EPS) * fmaxf(sqrtf(sse), EPS));
            acc.x *= w; acc.y *= w; acc.z *= w; acc.w *= w;

            if (FIN) {
                float4 a  = ldg_f4_pol((const float4*)(b0 + base) + hl, pF);
                float4 bb = ldg_f4_pol((const float4*)(b1 + base) + hl, pF);
                float4 cc = ldg_f4_pol((const float4*)(b2 + base) + hl, pF);
                acc.x += ev.x + a.x + bb.x + cc.x;
                acc.y += ev.y + a.y + bb.y + cc.y;
                acc.z += ev.z + a.z + bb.z + cc.z;
                acc.w += ev.w + a.w + bb.w + cc.w;
                ((float4*)(y + base))[hl] = acc;
                if (hl == 0) cnt[row] = 0;   // restore zero invariant
            } else {
                stg_f4_pol((float4*)(y + base) + hl, acc, pL);
            }
        }

        if (l < 3) grid_barrier(nblocks);
    }
}

extern "C" void kernel_launch(void* const* d_in, const int* in_sizes, int n_in,
                              void* d_out, int out_size) {
    const int*   adj_row  = (const int*)d_in[0];
    const int*   adj_col  = (const int*)d_in[1];
    const float* adj_val  = (const float*)d_in[2];
    const float* user_fea = (const float*)d_in[3];
    const float* item_fea = (const float*)d_in[4];
    const float* g_emb_u  = (const float*)d_in[5];
    const float* g_emb_i  = (const float*)d_in[6];
    const float* mlp_w    = (const float*)d_in[7];
    const float* mlp_b    = (const float*)d_in[8];
    float* acc = (float*)d_out;

    float *ego_p, *b0, *b1, *b2;
    int *cnt_p; int2 *elle_p;
    cudaGetSymbolAddress((void**)&ego_p,  g_ego);
    cudaGetSymbolAddress((void**)&b0,     g_buf0);
    cudaGetSymbolAddress((void**)&b1,     g_buf1);
    cudaGetSymbolAddress((void**)&b2,     g_buf2);
    cudaGetSymbolAddress((void**)&cnt_p,  g_cnt);
    cudaGetSymbolAddress((void**)&elle_p, g_elle);

    // cnt is zero on entry (zero-init on load; final layer restores it each call)
    k_preamble<<<PRE_BLOCKS, 256>>>(item_fea, mlp_w, mlp_b, g_emb_i,
                                    adj_row, adj_col, adj_val,
                                    user_fea, g_emb_u,
                                    cnt_p, elle_p, ego_p);

    // persistent grid: exactly-resident blocks (deadlock-safe for grid barrier)
    int dev = 0, nsm = 148, bpsm = 1;
    cudaGetDevice(&dev);
    cudaDeviceGetAttribute(&nsm, cudaDevAttrMultiProcessorCount, dev);
    cudaOccupancyMaxActiveBlocksPerMultiprocessor(&bpsm, k_layers, 256, 0);
    if (bpsm < 1) bpsm = 1;
    int nblocks = nsm * bpsm;

    k_layers<<<nblocks, 256>>>(ego_p, b0, b1, b2, acc, cnt_p, elle_p, nblocks);
}

// round 16
// speedup vs baseline: 1.3275x; 1.3275x over previous
#include <cuda_runtime.h>
#include <cuda_bf16.h>
#include <cuda_fp16.h>
#include <mma.h>
#include <math.h>
#include <stdint.h>

using namespace nvcuda;

#define U_NUM 100000
#define I_NUM 50000
#define N_NUM 150000
#define E_NUM 1200000
#define D 64
#define F_DIM 384
#define EPS 1e-8f
#define ELL_W 64

// Scratch (allocation-free rule: __device__ globals; zero-initialized at load)
// cnt invariant: zero at entry to every kernel_launch call.
__device__ float  g_ego[(size_t)N_NUM * D];          // fp32 ego (cosine + final combine)
__device__ __half g_egoh[(size_t)N_NUM * D];         // fp16 ego (layer-0 gather source)
__device__ __half g_bh0[(size_t)N_NUM * D];          // fp16 layer outputs
__device__ __half g_bh1[(size_t)N_NUM * D];
__device__ __half g_bh2[(size_t)N_NUM * D];
__device__ int    g_cnt[N_NUM];
__device__ int2   g_elle[(size_t)N_NUM * ELL_W];     // packed (col, val-bits); tail slots stay 0

__device__ __forceinline__ float tanh_fast(float x) {
    float r;
    asm("tanh.approx.f32 %0, %1;" : "=f"(r) : "f"(x));
    return r;
}

// ---- L2 cache-hint policies
__device__ __forceinline__ uint64_t mk_policy_last() {
    uint64_t p;
    asm("createpolicy.fractional.L2::evict_last.b64 %0, 1.0;" : "=l"(p));
    return p;
}
__device__ __forceinline__ uint64_t mk_policy_first() {
    uint64_t p;
    asm("createpolicy.fractional.L2::evict_first.b64 %0, 1.0;" : "=l"(p));
    return p;
}
__device__ __forceinline__ float4 ldg_f4_pol(const float4* p, uint64_t pol) {
    float4 v;
    asm("ld.global.nc.L2::cache_hint.v4.f32 {%0,%1,%2,%3}, [%4], %5;"
        : "=f"(v.x), "=f"(v.y), "=f"(v.z), "=f"(v.w) : "l"(p), "l"(pol));
    return v;
}
__device__ __forceinline__ int4 ldg_i4_pol(const int4* p, uint64_t pol) {
    int4 v;
    asm("ld.global.nc.L2::cache_hint.v4.b32 {%0,%1,%2,%3}, [%4], %5;"
        : "=r"(v.x), "=r"(v.y), "=r"(v.z), "=r"(v.w) : "l"(p), "l"(pol));
    return v;
}
// 8-byte fp16x4 gather (4 halves) with policy
__device__ __forceinline__ uint2 ldg_u2_pol(const uint2* p, uint64_t pol) {
    uint2 v;
    asm("ld.global.nc.L2::cache_hint.v2.b32 {%0,%1}, [%2], %3;"
        : "=r"(v.x), "=r"(v.y) : "l"(p), "l"(pol));
    return v;
}
__device__ __forceinline__ void stg_u2_pol(uint2* p, uint2 v, uint64_t pol) {
    asm volatile("st.global.L2::cache_hint.v2.b32 [%0], {%1,%2}, %3;"
                 :: "l"(p), "r"(v.x), "r"(v.y), "l"(pol) : "memory");
}
// half2 pair -> 4 floats
__device__ __forceinline__ void h4_to_f4(uint2 u, float& a, float& b, float& c, float& d) {
    __half2 h0 = *reinterpret_cast<__half2*>(&u.x);
    __half2 h1 = *reinterpret_cast<__half2*>(&u.y);
    float2 f0 = __half22float2(h0);
    float2 f1 = __half22float2(h1);
    a = f0.x; b = f0.y; c = f1.x; d = f1.y;
}
__device__ __forceinline__ uint2 f4_to_h4(float a, float b, float c, float d) {
    __half2 h0 = __floats2half2_rn(a, b);
    __half2 h1 = __floats2half2_rn(c, d);
    uint2 u;
    u.x = *reinterpret_cast<unsigned*>(&h0);
    u.y = *reinterpret_cast<unsigned*>(&h1);
    return u;
}

// ---------------- fused preamble: [gemm tiles | ELL build | user init]
#define BM 128
#define GK 32
#define LDA 40
#define LDW 40

#define GEMM_BLOCKS ((I_NUM + BM - 1) / BM)   // 391
#define BUILD_BLOCKS 320
#define USER_BLOCKS  320
#define PRE_BLOCKS (GEMM_BLOCKS + BUILD_BLOCKS + USER_BLOCKS)

#define SM_AS_HI 0
#define SM_AS_LO (SM_AS_HI + BM * LDA * 2)            // 10240
#define SM_WS_HI (SM_AS_LO + BM * LDA * 2)            // 20480
#define SM_WS_LO (SM_WS_HI + D * LDW * 2)             // 25600
#define SM_MAIN  (SM_WS_LO + D * LDW * 2)             // 30720
#define SM_TOTAL SM_MAIN

__device__ __forceinline__ void split_store(__nv_bfloat16* hi, __nv_bfloat16* lo, float v) {
    __nv_bfloat16 h = __float2bfloat16(v);
    *hi = h;
    *lo = __float2bfloat16(v - __bfloat162float(h));
}

__global__ __launch_bounds__(256) void k_preamble(
    const float* __restrict__ A,
    const float* __restrict__ W,
    const float* __restrict__ bias,
    const float* __restrict__ gi,
    const int* __restrict__ rows, const int* __restrict__ cols,
    const float* __restrict__ vals,
    const float* __restrict__ user_fea,
    const float* __restrict__ gu,
    int* __restrict__ cnt, int2* __restrict__ elle,
    float* __restrict__ ego, __half* __restrict__ egoh) {
    __shared__ __align__(16) char smem[SM_TOTAL];
    int blk = blockIdx.x;
    int t = threadIdx.x;

    if (blk < GEMM_BLOCKS) {
        __nv_bfloat16 (*AsH)[LDA] = (__nv_bfloat16(*)[LDA])(smem + SM_AS_HI);
        __nv_bfloat16 (*AsL)[LDA] = (__nv_bfloat16(*)[LDA])(smem + SM_AS_LO);
        __nv_bfloat16 (*WsH)[LDW] = (__nv_bfloat16(*)[LDW])(smem + SM_WS_HI);
        __nv_bfloat16 (*WsL)[LDW] = (__nv_bfloat16(*)[LDW])(smem + SM_WS_LO);

        int w = t >> 5;
        int lane = t & 31;
        int r0 = blk * BM;

        wmma::fragment<wmma::accumulator, 16, 16, 16, float> cfrag[4];
        #pragma unroll
        for (int nf = 0; nf < 4; nf++) wmma::fill_fragment(cfrag[nf], 0.0f);

        int ar = t >> 1,  ac = (t & 1) * 16;
        int wr = t >> 2,  wc = (t & 3) * 8;

        for (int k0 = 0; k0 < F_DIM; k0 += GK) {
            {
                int gr = r0 + ar;
                if (gr < I_NUM) {
                    const float4* src = (const float4*)(A + (size_t)gr * F_DIM + k0 + ac);
                    #pragma unroll
                    for (int s = 0; s < 4; s++) {
                        float4 v = __ldg(src + s);
                        split_store(&AsH[ar][ac + s * 4],     &AsL[ar][ac + s * 4],     v.x);
                        split_store(&AsH[ar][ac + s * 4 + 1], &AsL[ar][ac + s * 4 + 1], v.y);
                        split_store(&AsH[ar][ac + s * 4 + 2], &AsL[ar][ac + s * 4 + 2], v.z);
                        split_store(&AsH[ar][ac + s * 4 + 3], &AsL[ar][ac + s * 4 + 3], v.w);
                    }
                } else {
                    #pragma unroll
                    for (int s = 0; s < 16; s++) {
                        AsH[ar][ac + s] = __float2bfloat16(0.f);
                        AsL[ar][ac + s] = __float2bfloat16(0.f);
                    }
                }
            }
            {
                const float4* src = (const float4*)(W + (size_t)wr * F_DIM + k0 + wc);
                #pragma unroll
                for (int s = 0; s < 2; s++) {
                    float4 v = __ldg(src + s);
                    split_store(&WsH[wr][wc + s * 4],     &WsL[wr][wc + s * 4],     v.x);
                    split_store(&WsH[wr][wc + s * 4 + 1], &WsL[wr][wc + s * 4 + 1], v.y);
                    split_store(&WsH[wr][wc + s * 4 + 2], &WsL[wr][wc + s * 4 + 2], v.z);
                    split_store(&WsH[wr][wc + s * 4 + 3], &WsL[wr][wc + s * 4 + 3], v.w);
                }
            }
            __syncthreads();

            #pragma unroll
            for (int kk = 0; kk < GK; kk += 16) {
                wmma::fragment<wmma::matrix_a, 16, 16, 16, __nv_bfloat16, wmma::row_major> aH, aL;
                wmma::load_matrix_sync(aH, &AsH[w * 16][kk], LDA);
                wmma::load_matrix_sync(aL, &AsL[w * 16][kk], LDA);
                #pragma unroll
                for (int nf = 0; nf < 4; nf++) {
                    wmma::fragment<wmma::matrix_b, 16, 16, 16, __nv_bfloat16, wmma::col_major> bH, bL;
                    wmma::load_matrix_sync(bH, &WsH[nf * 16][kk], LDW);
                    wmma::load_matrix_sync(bL, &WsL[nf * 16][kk], LDW);
                    wmma::mma_sync(cfrag[nf], aH, bH, cfrag[nf]);
                    wmma::mma_sync(cfrag[nf], aH, bL, cfrag[nf]);
                    wmma::mma_sync(cfrag[nf], aL, bH, cfrag[nf]);
                }
            }
            __syncthreads();
        }

        // epilogue: per-warp 16x16 tile stash, sequential over nf (8KB, reuses staging smem)
        float (*OsW)[16][16] = (float(*)[16][16])smem;
        __syncthreads();
        #pragma unroll
        for (int nf = 0; nf < 4; nf++) {
            wmma::store_matrix_sync(&OsW[w][0][0], cfrag[nf], 16, wmma::mem_row_major);
            __syncwarp();
            for (int idx = lane; idx < 16 * 16; idx += 32) {
                int i = idx >> 4;
                int n = nf * 16 + (idx & 15);
                int r = r0 + w * 16 + i;
                if (r < I_NUM) {
                    float c = OsW[w][i][idx & 15];
                    float sn = gi[n] + gi[D + n] + gi[2 * D + n];
                    float v = tanh_fast(c + bias[n]) + sn;
                    size_t off = (size_t)(U_NUM + r) * D + n;
                    ego[off]  = v;
                    egoh[off] = __float2half_rn(v);
                }
            }
            __syncwarp();
        }
    } else if (blk < GEMM_BLOCKS + BUILD_BLOCKS) {
        int base = (blk - GEMM_BLOCKS) * 256 + t;
        for (int e = base; e < E_NUM; e += BUILD_BLOCKS * 256) {
            int r = __ldg(rows + e);
            int slot = atomicAdd(cnt + r, 1);
            if (slot < ELL_W) {
                int2 p;
                p.x = __ldg(cols + e);
                p.y = __float_as_int(__ldg(vals + e));
                elle[(size_t)r * ELL_W + slot] = p;
            }
        }
    } else {
        int wbase = (blk - GEMM_BLOCKS - BUILD_BLOCKS) * 8 + (t >> 5);
        int lane = t & 31;
        int d0 = lane * 2;
        float s0 = gu[d0]     + gu[D + d0]     + gu[2 * D + d0];
        float s1 = gu[d0 + 1] + gu[D + d0 + 1] + gu[2 * D + d0 + 1];
        for (int u = wbase; u < U_NUM; u += USER_BLOCKS * 8) {
            float2 v = ((const float2*)(user_fea + (size_t)u * D))[lane];
            v.x += s0; v.y += s1;
            size_t off = (size_t)u * D + d0;
            ((float2*)(g_ego + off))[0] = v;
            __half2 h = __floats2half2_rn(v.x, v.y);
            *reinterpret_cast<__half2*>(&g_egoh[off]) = h;
        }
    }
}

// ---------------- layer core: fp16 gathers, fp32 math  (half-warp per row)
// xh: fp16 gather source. Non-final: write yh fp16. Final: combine fp32 out.
template <bool FINAL>
__global__ __launch_bounds__(256, 8) void k_layer_t(
    const __half* __restrict__ xh, __half* __restrict__ yh,
    float* __restrict__ out,
    int* __restrict__ cnt, const int2* __restrict__ elle,
    const float* __restrict__ ego,
    const __half* __restrict__ h0, const __half* __restrict__ h1,
    const __half* __restrict__ h2) {
    int warp = (blockIdx.x * blockDim.x + threadIdx.x) >> 5;
    int lane = threadIdx.x & 31;
    int half_ = lane >> 4;
    int hl   = lane & 15;
    int row  = warp * 2 + half_;
    if (row >= N_NUM) return;

    uint64_t pL = mk_policy_last();
    uint64_t pF = mk_policy_first();

    int c = min(__ldg((const int*)cnt + row), ELL_W);
    const int4* ep4 = (const int4*)(elle + (size_t)row * ELL_W);
    float4 acc = make_float4(0.f, 0.f, 0.f, 0.f);

    int b = 0;
    do {
        int q = b >> 1;
        int4 q0 = ldg_i4_pol(ep4 + q,     pF);
        int4 q1 = ldg_i4_pol(ep4 + q + 1, pF);
        int4 q2 = ldg_i4_pol(ep4 + q + 2, pF);
        int4 q3 = ldg_i4_pol(ep4 + q + 3, pF);
        uint2 u0 = ldg_u2_pol((const uint2*)(xh + (size_t)q0.x * D) + hl, pL);
        uint2 u1 = ldg_u2_pol((const uint2*)(xh + (size_t)q0.z * D) + hl, pL);
        uint2 u2 = ldg_u2_pol((const uint2*)(xh + (size_t)q1.x * D) + hl, pL);
        uint2 u3 = ldg_u2_pol((const uint2*)(xh + (size_t)q1.z * D) + hl, pL);
        uint2 u4 = ldg_u2_pol((const uint2*)(xh + (size_t)q2.x * D) + hl, pL);
        uint2 u5 = ldg_u2_pol((const uint2*)(xh + (size_t)q2.z * D) + hl, pL);
        uint2 u6 = ldg_u2_pol((const uint2*)(xh + (size_t)q3.x * D) + hl, pL);
        uint2 u7 = ldg_u2_pol((const uint2*)(xh + (size_t)q3.z * D) + hl, pL);
        float v0 = __int_as_float(q0.y), v1 = __int_as_float(q0.w);
        float v2 = __int_as_float(q1.y), v3 = __int_as_float(q1.w);
        float v4 = __int_as_float(q2.y), v5 = __int_as_float(q2.w);
        float v6 = __int_as_float(q3.y), v7 = __int_as_float(q3.w);
        float a0, a1, a2, a3;
        h4_to_f4(u0, a0, a1, a2, a3);
        acc.x = fmaf(v0, a0, acc.x); acc.y = fmaf(v0, a1, acc.y);
        acc.z = fmaf(v0, a2, acc.z); acc.w = fmaf(v0, a3, acc.w);
        h4_to_f4(u1, a0, a1, a2, a3);
        acc.x = fmaf(v1, a0, acc.x); acc.y = fmaf(v1, a1, acc.y);
        acc.z = fmaf(v1, a2, acc.z); acc.w = fmaf(v1, a3, acc.w);
        h4_to_f4(u2, a0, a1, a2, a3);
        acc.x = fmaf(v2, a0, acc.x); acc.y = fmaf(v2, a1, acc.y);
        acc.z = fmaf(v2, a2, acc.z); acc.w = fmaf(v2, a3, acc.w);
        h4_to_f4(u3, a0, a1, a2, a3);
        acc.x = fmaf(v3, a0, acc.x); acc.y = fmaf(v3, a1, acc.y);
        acc.z = fmaf(v3, a2, acc.z); acc.w = fmaf(v3, a3, acc.w);
        h4_to_f4(u4, a0, a1, a2, a3);
        acc.x = fmaf(v4, a0, acc.x); acc.y = fmaf(v4, a1, acc.y);
        acc.z = fmaf(v4, a2, acc.z); acc.w = fmaf(v4, a3, acc.w);
        h4_to_f4(u5, a0, a1, a2, a3);
        acc.x = fmaf(v5, a0, acc.x); acc.y = fmaf(v5, a1, acc.y);
        acc.z = fmaf(v5, a2, acc.z); acc.w = fmaf(v5, a3, acc.w);
        h4_to_f4(u6, a0, a1, a2, a3);
        acc.x = fmaf(v6, a0, acc.x); acc.y = fmaf(v6, a1, acc.y);
        acc.z = fmaf(v6, a2, acc.z); acc.w = fmaf(v6, a3, acc.w);
        h4_to_f4(u7, a0, a1, a2, a3);
        acc.x = fmaf(v7, a0, acc.x); acc.y = fmaf(v7, a1, acc.y);
        acc.z = fmaf(v7, a2, acc.z); acc.w = fmaf(v7, a3, acc.w);
        b += 8;
    } while (b < c);

    size_t base = (size_t)row * D;
    float4 ev = ldg_f4_pol((const float4*)(ego + base) + hl, pF);
    float dot = acc.x * ev.x + acc.y * ev.y + acc.z * ev.z + acc.w * ev.w;
    float ssy = acc.x * acc.x + acc.y * acc.y + acc.z * acc.z + acc.w * acc.w;
    float sse = ev.x * ev.x + ev.y * ev.y + ev.z * ev.z + ev.w * ev.w;
    #pragma unroll
    for (int o = 8; o; o >>= 1) {
        dot += __shfl_xor_sync(0xffffffffu, dot, o);
        ssy += __shfl_xor_sync(0xffffffffu, ssy, o);
        sse += __shfl_xor_sync(0xffffffffu, sse, o);
    }
    float w = dot / (fmaxf(sqrtf(ssy), EPS) * fmaxf(sqrtf(sse), EPS));
    acc.x *= w; acc.y *= w; acc.z *= w; acc.w *= w;

    if (FINAL) {
        float b0a, b0b, b0c, b0d, b1a, b1b, b1c, b1d, b2a, b2b, b2c, b2d;
        h4_to_f4(ldg_u2_pol((const uint2*)(h0 + base) + hl, pF), b0a, b0b, b0c, b0d);
        h4_to_f4(ldg_u2_pol((const uint2*)(h1 + base) + hl, pF), b1a, b1b, b1c, b1d);
        h4_to_f4(ldg_u2_pol((const uint2*)(h2 + base) + hl, pF), b2a, b2b, b2c, b2d);
        acc.x += ev.x + b0a + b1a + b2a;
        acc.y += ev.y + b0b + b1b + b2b;
        acc.z += ev.z + b0c + b1c + b2c;
        acc.w += ev.w + b0d + b1d + b2d;
        ((float4*)(out + base))[hl] = acc;
        if (hl == 0) cnt[row] = 0;   // restore zero invariant
    } else {
        stg_u2_pol((uint2*)(yh + base) + hl, f4_to_h4(acc.x, acc.y, acc.z, acc.w), pL);
    }
}

extern "C" void kernel_launch(void* const* d_in, const int* in_sizes, int n_in,
                              void* d_out, int out_size) {
    const int*   adj_row  = (const int*)d_in[0];
    const int*   adj_col  = (const int*)d_in[1];
    const float* adj_val  = (const float*)d_in[2];
    const float* user_fea = (const float*)d_in[3];
    const float* item_fea = (const float*)d_in[4];
    const float* g_emb_u  = (const float*)d_in[5];
    const float* g_emb_i  = (const float*)d_in[6];
    const float* mlp_w    = (const float*)d_in[7];
    const float* mlp_b    = (const float*)d_in[8];
    float* acc = (float*)d_out;

    float *ego_p;
    __half *egoh_p, *h0, *h1, *h2;
    int *cnt_p; int2 *elle_p;
    cudaGetSymbolAddress((void**)&ego_p,  g_ego);
    cudaGetSymbolAddress((void**)&egoh_p, g_egoh);
    cudaGetSymbolAddress((void**)&h0,     g_bh0);
    cudaGetSymbolAddress((void**)&h1,     g_bh1);
    cudaGetSymbolAddress((void**)&h2,     g_bh2);
    cudaGetSymbolAddress((void**)&cnt_p,  g_cnt);
    cudaGetSymbolAddress((void**)&elle_p, g_elle);

    // cnt is zero on entry (zero-init on load; final layer restores it each call)
    k_preamble<<<PRE_BLOCKS, 256>>>(item_fea, mlp_w, mlp_b, g_emb_i,
                                    adj_row, adj_col, adj_val,
                                    user_fea, g_emb_u,
                                    cnt_p, elle_p, ego_p, egoh_p);

    int lgrid = (N_NUM / 2 + 7) / 8;
    k_layer_t<false><<<lgrid, 256>>>(egoh_p, h0, nullptr, cnt_p, elle_p, ego_p, h0, h1, h2);
    k_layer_t<false><<<lgrid, 256>>>(h0,     h1, nullptr, cnt_p, elle_p, ego_p, h0, h1, h2);
    k_layer_t<false><<<lgrid, 256>>>(h1,     h2, nullptr, cnt_p, elle_p, ego_p, h0, h1, h2);
    k_layer_t<true><<<lgrid, 256>>>(h2, nullptr, acc,     cnt_p, elle_p, ego_p, h0, h1, h2);
}

// round 17
// speedup vs baseline: 1.4271x; 1.0750x over previous
#include <cuda_runtime.h>
#include <cuda_bf16.h>
#include <cuda_fp16.h>
#include <mma.h>
#include <math.h>
#include <stdint.h>

using namespace nvcuda;

#define U_NUM 100000
#define I_NUM 50000
#define N_NUM 150000
#define E_NUM 1200000
#define D 64
#define F_DIM 384
#define EPS 1e-8f
#define ELL_W 64

// Scratch (allocation-free rule: __device__ globals; zero-initialized at load)
// cnt invariant: zero at entry to every kernel_launch call.
__device__ float  g_ego[(size_t)N_NUM * D];          // fp32 ego (final combine)
__device__ __half g_egoh[(size_t)N_NUM * D];         // fp16 ego (gathers + cosine)
__device__ __half g_bh0[(size_t)N_NUM * D];          // fp16 layer outputs
__device__ __half g_bh1[(size_t)N_NUM * D];
__device__ __half g_bh2[(size_t)N_NUM * D];
__device__ int    g_cnt[N_NUM];
__device__ int2   g_elle[(size_t)N_NUM * ELL_W];     // packed (col, val-bits); tail slots stay 0

__device__ __forceinline__ float tanh_fast(float x) {
    float r;
    asm("tanh.approx.f32 %0, %1;" : "=f"(r) : "f"(x));
    return r;
}

// ---- L2 cache-hint policies
__device__ __forceinline__ uint64_t mk_policy_last() {
    uint64_t p;
    asm("createpolicy.fractional.L2::evict_last.b64 %0, 1.0;" : "=l"(p));
    return p;
}
__device__ __forceinline__ uint64_t mk_policy_first() {
    uint64_t p;
    asm("createpolicy.fractional.L2::evict_first.b64 %0, 1.0;" : "=l"(p));
    return p;
}
__device__ __forceinline__ float4 ldg_f4_pol(const float4* p, uint64_t pol) {
    float4 v;
    asm("ld.global.nc.L2::cache_hint.v4.f32 {%0,%1,%2,%3}, [%4], %5;"
        : "=f"(v.x), "=f"(v.y), "=f"(v.z), "=f"(v.w) : "l"(p), "l"(pol));
    return v;
}
__device__ __forceinline__ int4 ldg_i4_pol(const int4* p, uint64_t pol) {
    int4 v;
    asm("ld.global.nc.L2::cache_hint.v4.b32 {%0,%1,%2,%3}, [%4], %5;"
        : "=r"(v.x), "=r"(v.y), "=r"(v.z), "=r"(v.w) : "l"(p), "l"(pol));
    return v;
}
__device__ __forceinline__ uint4 ldg_u4_pol(const uint4* p, uint64_t pol) {
    uint4 v;
    asm("ld.global.nc.L2::cache_hint.v4.b32 {%0,%1,%2,%3}, [%4], %5;"
        : "=r"(v.x), "=r"(v.y), "=r"(v.z), "=r"(v.w) : "l"(p), "l"(pol));
    return v;
}
__device__ __forceinline__ void stg_u4_pol(uint4* p, uint4 v, uint64_t pol) {
    asm volatile("st.global.L2::cache_hint.v4.b32 [%0], {%1,%2,%3,%4}, %5;"
                 :: "l"(p), "r"(v.x), "r"(v.y), "r"(v.z), "r"(v.w), "l"(pol) : "memory");
}
// uint4 (8 halves) -> 8 floats
__device__ __forceinline__ void h8_to_f8(uint4 u, float* f) {
    float2 t;
    t = __half22float2(*reinterpret_cast<__half2*>(&u.x)); f[0] = t.x; f[1] = t.y;
    t = __half22float2(*reinterpret_cast<__half2*>(&u.y)); f[2] = t.x; f[3] = t.y;
    t = __half22float2(*reinterpret_cast<__half2*>(&u.z)); f[4] = t.x; f[5] = t.y;
    t = __half22float2(*reinterpret_cast<__half2*>(&u.w)); f[6] = t.x; f[7] = t.y;
}
__device__ __forceinline__ uint4 f8_to_h8(const float* f) {
    __half2 h0 = __floats2half2_rn(f[0], f[1]);
    __half2 h1 = __floats2half2_rn(f[2], f[3]);
    __half2 h2 = __floats2half2_rn(f[4], f[5]);
    __half2 h3 = __floats2half2_rn(f[6], f[7]);
    uint4 u;
    u.x = *reinterpret_cast<unsigned*>(&h0);
    u.y = *reinterpret_cast<unsigned*>(&h1);
    u.z = *reinterpret_cast<unsigned*>(&h2);
    u.w = *reinterpret_cast<unsigned*>(&h3);
    return u;
}

// ---------------- fused preamble: [gemm tiles | ELL build | user init]
#define BM 128
#define GK 32
#define LDA 40
#define LDW 40

#define GEMM_BLOCKS ((I_NUM + BM - 1) / BM)   // 391
#define BUILD_BLOCKS 320
#define USER_BLOCKS  320
#define PRE_BLOCKS (GEMM_BLOCKS + BUILD_BLOCKS + USER_BLOCKS)

#define SM_AS_HI 0
#define SM_AS_LO (SM_AS_HI + BM * LDA * 2)            // 10240
#define SM_WS_HI (SM_AS_LO + BM * LDA * 2)            // 20480
#define SM_WS_LO (SM_WS_HI + D * LDW * 2)             // 25600
#define SM_MAIN  (SM_WS_LO + D * LDW * 2)             // 30720
#define SM_TOTAL SM_MAIN

__device__ __forceinline__ void split_store(__nv_bfloat16* hi, __nv_bfloat16* lo, float v) {
    __nv_bfloat16 h = __float2bfloat16(v);
    *hi = h;
    *lo = __float2bfloat16(v - __bfloat162float(h));
}

__global__ __launch_bounds__(256) void k_preamble(
    const float* __restrict__ A,
    const float* __restrict__ W,
    const float* __restrict__ bias,
    const float* __restrict__ gi,
    const int* __restrict__ rows, const int* __restrict__ cols,
    const float* __restrict__ vals,
    const float* __restrict__ user_fea,
    const float* __restrict__ gu,
    int* __restrict__ cnt, int2* __restrict__ elle,
    float* __restrict__ ego, __half* __restrict__ egoh) {
    __shared__ __align__(16) char smem[SM_TOTAL];
    int blk = blockIdx.x;
    int t = threadIdx.x;

    if (blk < GEMM_BLOCKS) {
        __nv_bfloat16 (*AsH)[LDA] = (__nv_bfloat16(*)[LDA])(smem + SM_AS_HI);
        __nv_bfloat16 (*AsL)[LDA] = (__nv_bfloat16(*)[LDA])(smem + SM_AS_LO);
        __nv_bfloat16 (*WsH)[LDW] = (__nv_bfloat16(*)[LDW])(smem + SM_WS_HI);
        __nv_bfloat16 (*WsL)[LDW] = (__nv_bfloat16(*)[LDW])(smem + SM_WS_LO);

        int w = t >> 5;
        int lane = t & 31;
        int r0 = blk * BM;

        wmma::fragment<wmma::accumulator, 16, 16, 16, float> cfrag[4];
        #pragma unroll
        for (int nf = 0; nf < 4; nf++) wmma::fill_fragment(cfrag[nf], 0.0f);

        int ar = t >> 1,  ac = (t & 1) * 16;
        int wr = t >> 2,  wc = (t & 3) * 8;

        for (int k0 = 0; k0 < F_DIM; k0 += GK) {
            {
                int gr = r0 + ar;
                if (gr < I_NUM) {
                    const float4* src = (const float4*)(A + (size_t)gr * F_DIM + k0 + ac);
                    #pragma unroll
                    for (int s = 0; s < 4; s++) {
                        float4 v = __ldg(src + s);
                        split_store(&AsH[ar][ac + s * 4],     &AsL[ar][ac + s * 4],     v.x);
                        split_store(&AsH[ar][ac + s * 4 + 1], &AsL[ar][ac + s * 4 + 1], v.y);
                        split_store(&AsH[ar][ac + s * 4 + 2], &AsL[ar][ac + s * 4 + 2], v.z);
                        split_store(&AsH[ar][ac + s * 4 + 3], &AsL[ar][ac + s * 4 + 3], v.w);
                    }
                } else {
                    #pragma unroll
                    for (int s = 0; s < 16; s++) {
                        AsH[ar][ac + s] = __float2bfloat16(0.f);
                        AsL[ar][ac + s] = __float2bfloat16(0.f);
                    }
                }
            }
            {
                const float4* src = (const float4*)(W + (size_t)wr * F_DIM + k0 + wc);
                #pragma unroll
                for (int s = 0; s < 2; s++) {
                    float4 v = __ldg(src + s);
                    split_store(&WsH[wr][wc + s * 4],     &WsL[wr][wc + s * 4],     v.x);
                    split_store(&WsH[wr][wc + s * 4 + 1], &WsL[wr][wc + s * 4 + 1], v.y);
                    split_store(&WsH[wr][wc + s * 4 + 2], &WsL[wr][wc + s * 4 + 2], v.z);
                    split_store(&WsH[wr][wc + s * 4 + 3], &WsL[wr][wc + s * 4 + 3], v.w);
                }
            }
            __syncthreads();

            #pragma unroll
            for (int kk = 0; kk < GK; kk += 16) {
                wmma::fragment<wmma::matrix_a, 16, 16, 16, __nv_bfloat16, wmma::row_major> aH, aL;
                wmma::load_matrix_sync(aH, &AsH[w * 16][kk], LDA);
                wmma::load_matrix_sync(aL, &AsL[w * 16][kk], LDA);
                #pragma unroll
                for (int nf = 0; nf < 4; nf++) {
                    wmma::fragment<wmma::matrix_b, 16, 16, 16, __nv_bfloat16, wmma::col_major> bH, bL;
                    wmma::load_matrix_sync(bH, &WsH[nf * 16][kk], LDW);
                    wmma::load_matrix_sync(bL, &WsL[nf * 16][kk], LDW);
                    wmma::mma_sync(cfrag[nf], aH, bH, cfrag[nf]);
                    wmma::mma_sync(cfrag[nf], aH, bL, cfrag[nf]);
                    wmma::mma_sync(cfrag[nf], aL, bH, cfrag[nf]);
                }
            }
            __syncthreads();
        }

        // epilogue: per-warp 16x16 tile stash, sequential over nf
        float (*OsW)[16][16] = (float(*)[16][16])smem;
        __syncthreads();
        #pragma unroll
        for (int nf = 0; nf < 4; nf++) {
            wmma::store_matrix_sync(&OsW[w][0][0], cfrag[nf], 16, wmma::mem_row_major);
            __syncwarp();
            for (int idx = lane; idx < 16 * 16; idx += 32) {
                int i = idx >> 4;
                int n = nf * 16 + (idx & 15);
                int r = r0 + w * 16 + i;
                if (r < I_NUM) {
                    float c = OsW[w][i][idx & 15];
                    float sn = gi[n] + gi[D + n] + gi[2 * D + n];
                    float v = tanh_fast(c + bias[n]) + sn;
                    size_t off = (size_t)(U_NUM + r) * D + n;
                    ego[off]  = v;
                    egoh[off] = __float2half_rn(v);
                }
            }
            __syncwarp();
        }
    } else if (blk < GEMM_BLOCKS + BUILD_BLOCKS) {
        int base = (blk - GEMM_BLOCKS) * 256 + t;
        for (int e = base; e < E_NUM; e += BUILD_BLOCKS * 256) {
            int r = __ldg(rows + e);
            int slot = atomicAdd(cnt + r, 1);
            if (slot < ELL_W) {
                int2 p;
                p.x = __ldg(cols + e);
                p.y = __float_as_int(__ldg(vals + e));
                elle[(size_t)r * ELL_W + slot] = p;
            }
        }
    } else {
        int wbase = (blk - GEMM_BLOCKS - BUILD_BLOCKS) * 8 + (t >> 5);
        int lane = t & 31;
        int d0 = lane * 2;
        float s0 = gu[d0]     + gu[D + d0]     + gu[2 * D + d0];
        float s1 = gu[d0 + 1] + gu[D + d0 + 1] + gu[2 * D + d0 + 1];
        for (int u = wbase; u < U_NUM; u += USER_BLOCKS * 8) {
            float2 v = ((const float2*)(user_fea + (size_t)u * D))[lane];
            v.x += s0; v.y += s1;
            size_t off = (size_t)u * D + d0;
            ((float2*)(g_ego + off))[0] = v;
            __half2 h = __floats2half2_rn(v.x, v.y);
            *reinterpret_cast<__half2*>(&g_egoh[off]) = h;
        }
    }
}

// ---------------- layer core: quarter-warp per row (8 lanes, LDG.128 fp16 gathers)
// Gathers in groups of 4 (16 regs live). Non-final: cosine vs fp16 ego; fp16 y.
// Final: fp32 ego + combine, fp32 out, cnt re-zero.
template <bool FINAL>
__global__ __launch_bounds__(256) void k_layer_t(
    const __half* __restrict__ xh, __half* __restrict__ yh,
    float* __restrict__ out,
    int* __restrict__ cnt, const int2* __restrict__ elle,
    const float* __restrict__ ego, const __half* __restrict__ egoh,
    const __half* __restrict__ h0, const __half* __restrict__ h1,
    const __half* __restrict__ h2) {
    int gq = (blockIdx.x * blockDim.x + threadIdx.x) >> 3;   // global quarter-warp id
    int ql = threadIdx.x & 7;
    int row = gq;
    if (row >= N_NUM) return;

    uint64_t pL = mk_policy_last();
    uint64_t pF = mk_policy_first();

    int c = min(__ldg((const int*)cnt + row), ELL_W);
    const int4* ep4 = (const int4*)(elle + (size_t)row * ELL_W);
    float acc[8];
    #pragma unroll
    for (int i = 0; i < 8; i++) acc[i] = 0.f;

    int b = 0;
    do {
        int q = b >> 1;
        int4 e0 = ldg_i4_pol(ep4 + q,     pF);
        int4 e1 = ldg_i4_pol(ep4 + q + 1, pF);
        int4 e2 = ldg_i4_pol(ep4 + q + 2, pF);
        int4 e3 = ldg_i4_pol(ep4 + q + 3, pF);
        // group A: edges 0-3
        {
            uint4 u0 = ldg_u4_pol((const uint4*)(xh + (size_t)e0.x * D) + ql, pL);
            uint4 u1 = ldg_u4_pol((const uint4*)(xh + (size_t)e0.z * D) + ql, pL);
            uint4 u2 = ldg_u4_pol((const uint4*)(xh + (size_t)e1.x * D) + ql, pL);
            uint4 u3 = ldg_u4_pol((const uint4*)(xh + (size_t)e1.z * D) + ql, pL);
            float v0 = __int_as_float(e0.y), v1 = __int_as_float(e0.w);
            float v2 = __int_as_float(e1.y), v3 = __int_as_float(e1.w);
            float f[8];
            h8_to_f8(u0, f);
            #pragma unroll
            for (int i = 0; i < 8; i++) acc[i] = fmaf(v0, f[i], acc[i]);
            h8_to_f8(u1, f);
            #pragma unroll
            for (int i = 0; i < 8; i++) acc[i] = fmaf(v1, f[i], acc[i]);
            h8_to_f8(u2, f);
            #pragma unroll
            for (int i = 0; i < 8; i++) acc[i] = fmaf(v2, f[i], acc[i]);
            h8_to_f8(u3, f);
            #pragma unroll
            for (int i = 0; i < 8; i++) acc[i] = fmaf(v3, f[i], acc[i]);
        }
        // group B: edges 4-7
        {
            uint4 u0 = ldg_u4_pol((const uint4*)(xh + (size_t)e2.x * D) + ql, pL);
            uint4 u1 = ldg_u4_pol((const uint4*)(xh + (size_t)e2.z * D) + ql, pL);
            uint4 u2 = ldg_u4_pol((const uint4*)(xh + (size_t)e3.x * D) + ql, pL);
            uint4 u3 = ldg_u4_pol((const uint4*)(xh + (size_t)e3.z * D) + ql, pL);
            float v4 = __int_as_float(e2.y), v5 = __int_as_float(e2.w);
            float v6 = __int_as_float(e3.y), v7 = __int_as_float(e3.w);
            float f[8];
            h8_to_f8(u0, f);
            #pragma unroll
            for (int i = 0; i < 8; i++) acc[i] = fmaf(v4, f[i], acc[i]);
            h8_to_f8(u1, f);
            #pragma unroll
            for (int i = 0; i < 8; i++) acc[i] = fmaf(v5, f[i], acc[i]);
            h8_to_f8(u2, f);
            #pragma unroll
            for (int i = 0; i < 8; i++) acc[i] = fmaf(v6, f[i], acc[i]);
            h8_to_f8(u3, f);
            #pragma unroll
            for (int i = 0; i < 8; i++) acc[i] = fmaf(v7, f[i], acc[i]);
        }
        b += 8;
    } while (b < c);

    size_t base = (size_t)row * D;
    float ev[8];
    float evf[8];  // fp32 ego for FINAL
    if (FINAL) {
        float4 a0 = ldg_f4_pol((const float4*)(ego + base) + 2 * ql,     pF);
        float4 a1 = ldg_f4_pol((const float4*)(ego + base) + 2 * ql + 1, pF);
        evf[0] = a0.x; evf[1] = a0.y; evf[2] = a0.z; evf[3] = a0.w;
        evf[4] = a1.x; evf[5] = a1.y; evf[6] = a1.z; evf[7] = a1.w;
        #pragma unroll
        for (int i = 0; i < 8; i++) ev[i] = evf[i];
    } else {
        uint4 ue = ldg_u4_pol((const uint4*)(egoh + base) + ql, pF);
        h8_to_f8(ue, ev);
    }

    float dot = 0.f, ssy = 0.f, sse = 0.f;
    #pragma unroll
    for (int i = 0; i < 8; i++) {
        dot = fmaf(acc[i], ev[i], dot);
        ssy = fmaf(acc[i], acc[i], ssy);
        sse = fmaf(ev[i], ev[i], sse);
    }
    #pragma unroll
    for (int o = 4; o; o >>= 1) {
        dot += __shfl_xor_sync(0xffffffffu, dot, o);
        ssy += __shfl_xor_sync(0xffffffffu, ssy, o);
        sse += __shfl_xor_sync(0xffffffffu, sse, o);
    }
    float w = dot / (fmaxf(sqrtf(ssy), EPS) * fmaxf(sqrtf(sse), EPS));
    #pragma unroll
    for (int i = 0; i < 8; i++) acc[i] *= w;

    if (FINAL) {
        float f0[8], f1[8], f2[8];
        h8_to_f8(ldg_u4_pol((const uint4*)(h0 + base) + ql, pF), f0);
        h8_to_f8(ldg_u4_pol((const uint4*)(h1 + base) + ql, pF), f1);
        h8_to_f8(ldg_u4_pol((const uint4*)(h2 + base) + ql, pF), f2);
        #pragma unroll
        for (int i = 0; i < 8; i++) acc[i] += evf[i] + f0[i] + f1[i] + f2[i];
        float4 o0, o1;
        o0.x = acc[0]; o0.y = acc[1]; o0.z = acc[2]; o0.w = acc[3];
        o1.x = acc[4]; o1.y = acc[5]; o1.z = acc[6]; o1.w = acc[7];
        ((float4*)(out + base))[2 * ql]     = o0;
        ((float4*)(out + base))[2 * ql + 1] = o1;
        if (ql == 0) cnt[row] = 0;   // restore zero invariant
    } else {
        stg_u4_pol((uint4*)(yh + base) + ql, f8_to_h8(acc), pL);
    }
}

extern "C" void kernel_launch(void* const* d_in, const int* in_sizes, int n_in,
                              void* d_out, int out_size) {
    const int*   adj_row  = (const int*)d_in[0];
    const int*   adj_col  = (const int*)d_in[1];
    const float* adj_val  = (const float*)d_in[2];
    const float* user_fea = (const float*)d_in[3];
    const float* item_fea = (const float*)d_in[4];
    const float* g_emb_u  = (const float*)d_in[5];
    const float* g_emb_i  = (const float*)d_in[6];
    const float* mlp_w    = (const float*)d_in[7];
    const float* mlp_b    = (const float*)d_in[8];
    float* acc = (float*)d_out;

    float *ego_p;
    __half *egoh_p, *h0, *h1, *h2;
    int *cnt_p; int2 *elle_p;
    cudaGetSymbolAddress((void**)&ego_p,  g_ego);
    cudaGetSymbolAddress((void**)&egoh_p, g_egoh);
    cudaGetSymbolAddress((void**)&h0,     g_bh0);
    cudaGetSymbolAddress((void**)&h1,     g_bh1);
    cudaGetSymbolAddress((void**)&h2,     g_bh2);
    cudaGetSymbolAddress((void**)&cnt_p,  g_cnt);
    cudaGetSymbolAddress((void**)&elle_p, g_elle);

    // cnt is zero on entry (zero-init on load; final layer restores it each call)
    k_preamble<<<PRE_BLOCKS, 256>>>(item_fea, mlp_w, mlp_b, g_emb_i,
                                    adj_row, adj_col, adj_val,
                                    user_fea, g_emb_u,
                                    cnt_p, elle_p, ego_p, egoh_p);

    int lgrid = (N_NUM * 8 + 255) / 256;   // quarter-warp per row
    k_layer_t<false><<<lgrid, 256>>>(egoh_p, h0, nullptr, cnt_p, elle_p, ego_p, egoh_p, h0, h1, h2);
    k_layer_t<false><<<lgrid, 256>>>(h0,     h1, nullptr, cnt_p, elle_p, ego_p, egoh_p, h0, h1, h2);
    k_layer_t<false><<<lgrid, 256>>>(h1,     h2, nullptr, cnt_p, elle_p, ego_p, egoh_p, h0, h1, h2);
    k_layer_t<true><<<lgrid, 256>>>(h2, nullptr, acc,     cnt_p, elle_p, ego_p, egoh_p, h0, h1, h2);
}